// round 13
// baseline (speedup 1.0000x reference)
#include <cuda_runtime.h>
#include <cstdint>

// Problem constants (fixed by the reference)
#define E    1024
#define NBLK 6
#define FF   4096
#define CC   1000
#define BB   4096

// ---------------- device scratch (no allocations allowed) ----------------
__device__ __align__(16) float g_M[NBLK * E * 8]; // precomputed Wo@Wv (E x 8 per block)
__device__ __align__(16) float g_f[2][E];         // f vector, double-buffered by parity
__device__ __align__(16) float g_h1[2][E];        // h-after-LN1, double-buffered
__device__ __align__(16) float g_row[CC];         // classifier row

__device__ __forceinline__ float dot4(float4 a, float4 b) {
    return fmaf(a.x, b.x, fmaf(a.y, b.y, fmaf(a.z, b.z, a.w * b.w)));
}

// LayerNorm stats over E values (one per thread, 1024 threads).
__device__ __forceinline__ void ln_stats(float val, float* red1, float* red2,
                                         float* stats, int lane, int wc) {
    float s1 = val, s2 = val * val;
#pragma unroll
    for (int o = 16; o; o >>= 1) {
        s1 += __shfl_xor_sync(0xffffffffu, s1, o);
        s2 += __shfl_xor_sync(0xffffffffu, s2, o);
    }
    if (lane == 0) { red1[wc] = s1; red2[wc] = s2; }
    __syncthreads();
    if (wc == 0) {
        float a = red1[lane], c = red2[lane];
#pragma unroll
        for (int o = 16; o; o >>= 1) {
            a += __shfl_xor_sync(0xffffffffu, a, o);
            c += __shfl_xor_sync(0xffffffffu, c, o);
        }
        if (lane == 0) {
            float mean = a * (1.0f / E);
            float var  = c * (1.0f / E) - mean * mean;
            stats[0] = mean;
            stats[1] = rsqrtf(fmaxf(var, 0.f) + 1e-5f);
        }
    }
    __syncthreads();
}

// ================= K_M0: M_0 = Wo_0 @ Wv_0 only  ===========================
// grid = 32 CTAs x 256 threads: CTA c -> rows c*32 .. +32. (M_1..M_5 are
// computed inside kf_0..kf_4 by their idle warps, overlapping W2 traffic.)
__global__ void __launch_bounds__(256)
km_kernel(const float* __restrict__ Wo, const float* __restrict__ Wv)
{
    __shared__ __align__(16) float wv_s[E * 8];   // 32KB
    const int tid = threadIdx.x, lane = tid & 31, w = tid >> 5;
    const int row0 = blockIdx.x * 32;

    const float4* wvg = (const float4*)Wv;        // block 0
    float4* wv4 = (float4*)wv_s;
    for (int i = tid; i < E * 8 / 4; i += 256) wv4[i] = wvg[i];
    __syncthreads();

    const int r0 = row0 + 4 * w;
    const float* wo0 = Wo + (size_t)r0 * E;       // block 0

    float acc[4][8];
#pragma unroll
    for (int r = 0; r < 4; r++)
#pragma unroll
        for (int j = 0; j < 8; j++) acc[r][j] = 0.f;

#pragma unroll
    for (int kk = 0; kk < 8; kk++) {
        int k4 = lane + 32 * kk;
        float4 wo4[4];
#pragma unroll
        for (int r = 0; r < 4; r++)
            wo4[r] = __ldcs((const float4*)(wo0 + (size_t)r * E) + k4);
#pragma unroll
        for (int q = 0; q < 4; q++) {
            int k = 4 * k4 + q;
            float4 a = wv4[2 * k], c = wv4[2 * k + 1];
#pragma unroll
            for (int r = 0; r < 4; r++) {
                float s = (q == 0) ? wo4[r].x : (q == 1) ? wo4[r].y
                        : (q == 2) ? wo4[r].z : wo4[r].w;
                acc[r][0] = fmaf(s, a.x, acc[r][0]);
                acc[r][1] = fmaf(s, a.y, acc[r][1]);
                acc[r][2] = fmaf(s, a.z, acc[r][2]);
                acc[r][3] = fmaf(s, a.w, acc[r][3]);
                acc[r][4] = fmaf(s, c.x, acc[r][4]);
                acc[r][5] = fmaf(s, c.y, acc[r][5]);
                acc[r][6] = fmaf(s, c.z, acc[r][6]);
                acc[r][7] = fmaf(s, c.w, acc[r][7]);
            }
        }
    }
#pragma unroll
    for (int r = 0; r < 4; r++) {
#pragma unroll
        for (int j = 0; j < 8; j++) {
#pragma unroll
            for (int o = 16; o; o >>= 1)
                acc[r][j] += __shfl_xor_sync(0xffffffffu, acc[r][j], o);
        }
        if (lane == 0) {
            float4* mrow = (float4*)(g_M + (size_t)(r0 + r) * 8);
            mrow[0] = make_float4(acc[r][0], acc[r][1], acc[r][2], acc[r][3]);
            mrow[1] = make_float4(acc[r][4], acc[r][5], acc[r][6], acc[r][7]);
        }
    }
}

// ================= K_F(blk): one transformer block ==========================
// grid = 148 CTAs x 1024. CTA b owns W2 rows [7b, 7b+7) -> 28 active warps.
// The 4 idle warps (i==7) compute M_{blk+1} rows [7b, 7b+7) during phase 3,
// creating a second concurrent read stream (Wo, __ldcs) alongside W2 —
// the dual-stream pattern that measured 2.08 TB/s in R9.
__global__ void __launch_bounds__(1024)
kf_kernel(int blk,
          const float* __restrict__ W1,   const float* __restrict__ W2,
          const float* __restrict__ Wo,   const float* __restrict__ Wv,
          const float* __restrict__ phi_q, const float* __restrict__ phi_f,
          const float* __restrict__ ln1_g, const float* __restrict__ ln1_b,
          const float* __restrict__ ln2_g, const float* __restrict__ ln2_b)
{
    __shared__ __align__(16) float r_s[FF];
    __shared__ __align__(16) float h_s[E];
    __shared__ float red1[32], red2[32], stats[2], m_s[8];
    __shared__ float red_dot[7][4];

    const int tid = threadIdx.x, lane = tid & 31, wc = tid >> 5;
    const int b = blockIdx.x;
    const int cur = blk & 1, prev = (blk + 1) & 1;

    const int i = wc >> 2;                 // 0..7 row within CTA (7 valid)
    const int p = wc & 3;                  // 0..3 row segment
    const int row = b * 7 + i;
    const bool active = (i < 7) && (row < E);

    // ---- 1) issue W2 row-slice loads into registers (fire-and-forget) ----
    float4 wreg[8];
    if (active) {
        const float4* src = (const float4*)W2 + (size_t)blk * E * (FF / 4)
                          + (size_t)row * (FF / 4) + p * 256 + lane;
#pragma unroll
        for (int j = 0; j < 8; j++) wreg[j] = src[32 * j];
    }

    // ---- 2) prologue (overlaps the in-flight loads) ----
    float hp;
    if (blk == 0) {
        hp = 1.0f + (float)(tid & 1);                    // h0 = [1,2,1,2,...]
    } else {
        float val = g_h1[prev][tid] + g_f[prev][tid];
        ln_stats(val, red1, red2, stats, lane, wc);
        hp = (val - stats[0]) * stats[1] * ln2_g[(blk - 1) * E + tid]
           + ln2_b[(blk - 1) * E + tid];
    }
    h_s[tid] = hp;
    __syncthreads();
    if (tid < 8) m_s[tid] = cosf(h_s[tid] + phi_q[blk * 8 + tid]);
    __syncthreads();
    float attn;
    {
        const float4* mrow = (const float4*)(g_M + ((size_t)blk * E + tid) * 8);
        float4 a = mrow[0], c = mrow[1];
        attn = a.x * m_s[0] + a.y * m_s[1] + a.z * m_s[2] + a.w * m_s[3]
             + c.x * m_s[4] + c.y * m_s[5] + c.z * m_s[6] + c.w * m_s[7];
    }
    float h1;
    {
        float val = hp + attn;
        ln_stats(val, red1, red2, stats, lane, wc);
        h1 = (val - stats[0]) * stats[1] * ln1_g[blk * E + tid]
           + ln1_b[blk * E + tid];
    }
    if (b == 0) g_h1[cur][tid] = h1;                      // for next node
    h_s[tid] = h1;
    __syncthreads();
    if (tid < 4) m_s[tid] = cosf(h_s[tid]) * cosf(phi_f[blk * 4 + tid]);
    __syncthreads();
    {
        const float4* w1 = (const float4*)W1 + (size_t)blk * FF;  // FF float4 rows
        float m0 = m_s[0], m1 = m_s[1], m2 = m_s[2], m3 = m_s[3];
#pragma unroll
        for (int j = 0; j < FF / 1024; j++) {
            int ff = tid + j * 1024;
            float4 w = w1[ff];
            r_s[ff] = fmaxf(w.x * m0 + w.y * m1 + w.z * m2 + w.w * m3, 0.f);
        }
    }
    __syncthreads();

    // ---- 3) W2-warps: dot register slice vs r.  M-warps: compute M_{blk+1} ----
    if (active) {
        const float4* r4 = (const float4*)r_s;
        float acc = 0.f;
#pragma unroll
        for (int j = 0; j < 8; j++)
            acc += dot4(wreg[j], r4[p * 256 + lane + 32 * j]);
#pragma unroll
        for (int o = 16; o; o >>= 1) acc += __shfl_xor_sync(0xffffffffu, acc, o);
        if (lane == 0) red_dot[i][p] = acc;
    } else if (blk < NBLK - 1) {
        // warps 28..31: 2 row-slots each; need slots 0..6 (rows [7b, 7b+7))
        const int nblk = blk + 1;
        const float4* wv = (const float4*)(Wv + (size_t)nblk * E * 8);
#pragma unroll
        for (int rep = 0; rep < 2; rep++) {
            int slot = (wc - 28) * 2 + rep;
            int mrow = b * 7 + slot;
            if (slot < 7 && mrow < E) {
                const float4* wo = (const float4*)(Wo + ((size_t)nblk * E + mrow) * E);
                float acc[8];
#pragma unroll
                for (int j = 0; j < 8; j++) acc[j] = 0.f;
#pragma unroll
                for (int kk = 0; kk < 8; kk++) {
                    float4 o4 = __ldcs(wo + lane + 32 * kk);
#pragma unroll
                    for (int q = 0; q < 4; q++) {
                        int k = 4 * (lane + 32 * kk) + q;
                        float s = (q == 0) ? o4.x : (q == 1) ? o4.y
                                : (q == 2) ? o4.z : o4.w;
                        float4 a = __ldg(wv + 2 * k);
                        float4 c = __ldg(wv + 2 * k + 1);
                        acc[0] = fmaf(s, a.x, acc[0]);
                        acc[1] = fmaf(s, a.y, acc[1]);
                        acc[2] = fmaf(s, a.z, acc[2]);
                        acc[3] = fmaf(s, a.w, acc[3]);
                        acc[4] = fmaf(s, c.x, acc[4]);
                        acc[5] = fmaf(s, c.y, acc[5]);
                        acc[6] = fmaf(s, c.z, acc[6]);
                        acc[7] = fmaf(s, c.w, acc[7]);
                    }
                }
#pragma unroll
                for (int j = 0; j < 8; j++) {
#pragma unroll
                    for (int o = 16; o; o >>= 1)
                        acc[j] += __shfl_xor_sync(0xffffffffu, acc[j], o);
                }
                if (lane == 0) {
                    float4* mr = (float4*)(g_M + ((size_t)nblk * E + mrow) * 8);
                    mr[0] = make_float4(acc[0], acc[1], acc[2], acc[3]);
                    mr[1] = make_float4(acc[4], acc[5], acc[6], acc[7]);
                }
            }
        }
    }
    __syncthreads();
    if (tid < 7 && b * 7 + tid < E) {
        float s = red_dot[tid][0] + red_dot[tid][1] + red_dot[tid][2] + red_dot[tid][3];
        g_f[cur][b * 7 + tid] = s;
    }
}

// ================= K_CLS: LN2-final + classifier ===========================
// grid = 125 CTAs x 1024. CTA b owns Wc rows [8b, 8b+8).
__global__ void __launch_bounds__(1024)
kcls_kernel(const float* __restrict__ Wc, const float* __restrict__ bc,
            const float* __restrict__ ln2_g, const float* __restrict__ ln2_b)
{
    __shared__ __align__(16) float h_s[E];
    __shared__ float red1[32], red2[32], stats[2];
    __shared__ float red_cls[8][4];

    const int tid = threadIdx.x, lane = tid & 31, wc = tid >> 5;
    const int b = blockIdx.x;
    const int r = wc >> 2, p = wc & 3;         // 8 rows x 4 warp-parts

    // issue Wc loads into registers first (overlap with LN)
    float4 w0, w1;
    {
        const float4* src = (const float4*)Wc + ((size_t)b * 8 + r) * 256;
        w0 = src[p * 64 + lane];
        w1 = src[p * 64 + lane + 32];
    }

    // h_final = LN2 of block 5 (parity: 5&1 = 1)
    {
        float val = g_h1[1][tid] + g_f[1][tid];
        ln_stats(val, red1, red2, stats, lane, wc);
        h_s[tid] = (val - stats[0]) * stats[1] * ln2_g[5 * E + tid]
                 + ln2_b[5 * E + tid];
    }
    __syncthreads();

    const float4* h4 = (const float4*)h_s;
    float acc = dot4(w0, h4[p * 64 + lane]) + dot4(w1, h4[p * 64 + lane + 32]);
#pragma unroll
    for (int o = 16; o; o >>= 1) acc += __shfl_xor_sync(0xffffffffu, acc, o);
    if (lane == 0) red_cls[r][p] = acc;
    __syncthreads();
    if (tid < 8) {
        float s = red_cls[tid][0] + red_cls[tid][1] + red_cls[tid][2] + red_cls[tid][3];
        g_row[b * 8 + tid] = s + bc[b * 8 + tid];
    }
}

// ================= K_BCAST: broadcast row to all B output rows =============
// __stwt: write-through, no L2 allocation.
__global__ void __launch_bounds__(1024)
kb_kernel(float* __restrict__ out)
{
    __shared__ __align__(16) float row_s[CC];
    const int tid = threadIdx.x, lane = tid & 31;
    if (tid < CC) row_s[tid] = g_row[tid];
    __syncthreads();

    const int gwarp = blockIdx.x * 32 + (tid >> 5);
    const int nwarps = gridDim.x * 32;
    const float4* r4 = (const float4*)row_s;               // 250 float4
    for (int r = gwarp; r < BB; r += nwarps) {
        float4* dst = (float4*)out + (size_t)r * (CC / 4);
        for (int j = lane; j < CC / 4; j += 32)
            __stwt(dst + j, r4[j]);
    }
}

// ================= host launch =============================================
extern "C" void kernel_launch(void* const* d_in, const int* in_sizes, int n_in,
                              void* d_out, int out_size) {
    // metadata order: 0:x 1:Wq 2:Wk 3:Wv 4:Wo 5:phi_q 6:W1 7:W2 8:phi_f
    //                 9:ln1_g 10:ln1_b 11:ln2_g 12:ln2_b 13:Wc 14:bc
    const float* Wv    = (const float*)d_in[3];
    const float* Wo    = (const float*)d_in[4];
    const float* phi_q = (const float*)d_in[5];
    const float* W1    = (const float*)d_in[6];
    const float* W2    = (const float*)d_in[7];
    const float* phi_f = (const float*)d_in[8];
    const float* ln1_g = (const float*)d_in[9];
    const float* ln1_b = (const float*)d_in[10];
    const float* ln2_g = (const float*)d_in[11];
    const float* ln2_b = (const float*)d_in[12];
    const float* Wc    = (const float*)d_in[13];
    const float* bc    = (const float*)d_in[14];

    km_kernel<<<32, 256>>>(Wo, Wv);
    for (int blk = 0; blk < NBLK; blk++)
        kf_kernel<<<148, 1024>>>(blk, W1, W2, Wo, Wv, phi_q, phi_f,
                                 ln1_g, ln1_b, ln2_g, ln2_b);
    kcls_kernel<<<125, 1024>>>(Wc, bc, ln2_g, ln2_b);
    kb_kernel<<<148, 1024>>>((float*)d_out);
}

// round 14
// speedup vs baseline: 2.7312x; 2.7312x over previous
#include <cuda_runtime.h>
#include <cstdint>

// Problem constants (fixed by the reference)
#define E    1024
#define NBLK 6
#define FF   4096
#define CC   1000
#define BB   4096

// ---------------- device scratch (no allocations allowed) ----------------
__device__ __align__(16) float g_M[NBLK * E * 8]; // precomputed Wo@Wv (E x 8 per block)
__device__ __align__(16) float g_f[2][E];         // f vector, double-buffered by parity
__device__ __align__(16) float g_h1[2][E];        // h-after-LN1, double-buffered
__device__ __align__(16) float g_row[CC];         // classifier row

__device__ __forceinline__ float dot4(float4 a, float4 b) {
    return fmaf(a.x, b.x, fmaf(a.y, b.y, fmaf(a.z, b.z, a.w * b.w)));
}

// LN stats over 1024 values held 4-per-thread by 256 threads.
// Leaves mean in stats[0], rstd in stats[1].
__device__ __forceinline__ void ln_stats256(float4 v, float* red1, float* red2,
                                            float* stats, int lane, int w) {
    float s1 = v.x + v.y + v.z + v.w;
    float s2 = v.x*v.x + v.y*v.y + v.z*v.z + v.w*v.w;
#pragma unroll
    for (int o = 16; o; o >>= 1) {
        s1 += __shfl_xor_sync(0xffffffffu, s1, o);
        s2 += __shfl_xor_sync(0xffffffffu, s2, o);
    }
    if (lane == 0) { red1[w] = s1; red2[w] = s2; }
    __syncthreads();
    if (w == 0 && lane == 0) {
        float t1 = 0.f, t2 = 0.f;
#pragma unroll
        for (int i = 0; i < 8; i++) { t1 += red1[i]; t2 += red2[i]; }
        float mean = t1 * (1.0f / E);
        float var  = t2 * (1.0f / E) - mean * mean;
        stats[0] = mean;
        stats[1] = rsqrtf(fmaxf(var, 0.f) + 1e-5f);
    }
    __syncthreads();
}

// ================= K_M: M_blk = Wo_blk @ Wv_blk  (all 6 blocks) ============
// grid = 192 CTAs x 256: CTA c -> blk = c/32, rows (c%32)*32 .. +32.
// This kernel's pipelined 4-row load-FMA loop is the fast streaming shape.
__global__ void __launch_bounds__(256)
km_kernel(const float* __restrict__ Wo, const float* __restrict__ Wv)
{
    __shared__ __align__(16) float wv_s[E * 8];   // 32KB
    const int tid = threadIdx.x, lane = tid & 31, w = tid >> 5;
    const int blk  = blockIdx.x >> 5;
    const int row0 = (blockIdx.x & 31) * 32;

    const float4* wvg = (const float4*)(Wv + (size_t)blk * E * 8);
    float4* wv4 = (float4*)wv_s;
    for (int i = tid; i < E * 8 / 4; i += 256) wv4[i] = wvg[i];
    __syncthreads();

    const int r0 = row0 + 4 * w;
    const float* wo0 = Wo + (size_t)blk * E * E + (size_t)r0 * E;

    float acc[4][8];
#pragma unroll
    for (int r = 0; r < 4; r++)
#pragma unroll
        for (int j = 0; j < 8; j++) acc[r][j] = 0.f;

#pragma unroll
    for (int kk = 0; kk < 8; kk++) {
        int k4 = lane + 32 * kk;
        float4 wo4[4];
#pragma unroll
        for (int r = 0; r < 4; r++)
            wo4[r] = __ldcs((const float4*)(wo0 + (size_t)r * E) + k4);
#pragma unroll
        for (int q = 0; q < 4; q++) {
            int k = 4 * k4 + q;
            float4 a = wv4[2 * k], c = wv4[2 * k + 1];
#pragma unroll
            for (int r = 0; r < 4; r++) {
                float s = (q == 0) ? wo4[r].x : (q == 1) ? wo4[r].y
                        : (q == 2) ? wo4[r].z : wo4[r].w;
                acc[r][0] = fmaf(s, a.x, acc[r][0]);
                acc[r][1] = fmaf(s, a.y, acc[r][1]);
                acc[r][2] = fmaf(s, a.z, acc[r][2]);
                acc[r][3] = fmaf(s, a.w, acc[r][3]);
                acc[r][4] = fmaf(s, c.x, acc[r][4]);
                acc[r][5] = fmaf(s, c.y, acc[r][5]);
                acc[r][6] = fmaf(s, c.z, acc[r][6]);
                acc[r][7] = fmaf(s, c.w, acc[r][7]);
            }
        }
    }
#pragma unroll
    for (int r = 0; r < 4; r++) {
#pragma unroll
        for (int j = 0; j < 8; j++) {
#pragma unroll
            for (int o = 16; o; o >>= 1)
                acc[r][j] += __shfl_xor_sync(0xffffffffu, acc[r][j], o);
        }
        if (lane == 0) {
            float4* mrow = (float4*)(g_M + ((size_t)blk * E + r0 + r) * 8);
            mrow[0] = make_float4(acc[r][0], acc[r][1], acc[r][2], acc[r][3]);
            mrow[1] = make_float4(acc[r][4], acc[r][5], acc[r][6], acc[r][7]);
        }
    }
}

// ================= K_F(blk): one transformer block ==========================
// grid = 147 CTAs x 256 threads. Prologue first (cheap at 256 threads), then
// the dot runs as a PIPELINED full-row loop: warp = one W2 row, 32 float4
// loads per lane interleaved with FMAs — the same continuous streaming shape
// as km (which achieves ~2x the bandwidth of a one-shot register burst).
__global__ void __launch_bounds__(256)
kf_kernel(int blk,
          const float* __restrict__ W1,   const float* __restrict__ W2,
          const float* __restrict__ phi_q, const float* __restrict__ phi_f,
          const float* __restrict__ ln1_g, const float* __restrict__ ln1_b,
          const float* __restrict__ ln2_g, const float* __restrict__ ln2_b)
{
    __shared__ __align__(16) float r_s[FF];       // 16KB
    __shared__ float red1[8], red2[8], stats[2], h8[8], mq[8], mf[4];

    const int tid = threadIdx.x, lane = tid & 31, w = tid >> 5;
    const int b = blockIdx.x;
    const int cur = blk & 1, prev = cur ^ 1;

    // ---- prologue: h_in (4 vals/thread as float4 index tid) ----
    float4 hin;
    if (blk == 0) {
        hin = make_float4(1.f, 2.f, 1.f, 2.f);          // h0 = 1 + pe0
    } else {
        float4 a = ((const float4*)g_h1[prev])[tid];
        float4 c = ((const float4*)g_f[prev])[tid];
        hin = make_float4(a.x + c.x, a.y + c.y, a.z + c.z, a.w + c.w);
        ln_stats256(hin, red1, red2, stats, lane, w);
        float mean = stats[0], rstd = stats[1];
        float4 g4 = ((const float4*)(ln2_g + (size_t)(blk - 1) * E))[tid];
        float4 b4 = ((const float4*)(ln2_b + (size_t)(blk - 1) * E))[tid];
        hin.x = (hin.x - mean) * rstd * g4.x + b4.x;
        hin.y = (hin.y - mean) * rstd * g4.y + b4.y;
        hin.z = (hin.z - mean) * rstd * g4.z + b4.z;
        hin.w = (hin.w - mean) * rstd * g4.w + b4.w;
    }
    if (tid < 2) {
        h8[4 * tid + 0] = hin.x; h8[4 * tid + 1] = hin.y;
        h8[4 * tid + 2] = hin.z; h8[4 * tid + 3] = hin.w;
    }
    __syncthreads();
    if (tid < 8) mq[tid] = cosf(h8[tid] + phi_q[blk * 8 + tid]);
    __syncthreads();

    // attn for rows 4*tid .. 4*tid+3 via M_blk
    float m0 = mq[0], m1 = mq[1], m2 = mq[2], m3 = mq[3];
    float m4 = mq[4], m5 = mq[5], m6 = mq[6], m7 = mq[7];
    float at[4];
#pragma unroll
    for (int j = 0; j < 4; j++) {
        const float4* mr = (const float4*)(g_M + ((size_t)blk * E + 4 * tid + j) * 8);
        float4 a = mr[0], c = mr[1];
        at[j] = a.x*m0 + a.y*m1 + a.z*m2 + a.w*m3
              + c.x*m4 + c.y*m5 + c.z*m6 + c.w*m7;
    }
    float4 v = make_float4(hin.x + at[0], hin.y + at[1], hin.z + at[2], hin.w + at[3]);
    ln_stats256(v, red1, red2, stats, lane, w);
    {
        float mean = stats[0], rstd = stats[1];
        float4 g4 = ((const float4*)(ln1_g + (size_t)blk * E))[tid];
        float4 b4 = ((const float4*)(ln1_b + (size_t)blk * E))[tid];
        v.x = (v.x - mean) * rstd * g4.x + b4.x;
        v.y = (v.y - mean) * rstd * g4.y + b4.y;
        v.z = (v.z - mean) * rstd * g4.z + b4.z;
        v.w = (v.w - mean) * rstd * g4.w + b4.w;
    }
    if (b == 0) ((float4*)g_h1[cur])[tid] = v;            // for next node / kcls
    if (tid == 0) { h8[0] = v.x; h8[1] = v.y; h8[2] = v.z; h8[3] = v.w; }
    __syncthreads();
    if (tid < 4) mf[tid] = cosf(h8[tid]) * cosf(phi_f[blk * 4 + tid]);
    __syncthreads();

    // r = relu(W1 @ m): 16 outputs per thread, coalesced
    {
        const float4* w1 = (const float4*)W1 + (size_t)blk * FF;  // FF float4 rows
        float f0 = mf[0], f1 = mf[1], f2 = mf[2], f3 = mf[3];
#pragma unroll
        for (int j = 0; j < 16; j++) {
            int ff = tid + 256 * j;
            float4 wv = w1[ff];
            r_s[ff] = fmaxf(wv.x*f0 + wv.y*f1 + wv.z*f2 + wv.w*f3, 0.f);
        }
    }
    __syncthreads();

    // ---- dot: warp = one full W2 row, pipelined 32-load loop ----
    const int row = b * 7 + w;
    if (w < 7 && row < E) {
        const float4* wrow = (const float4*)W2 + (size_t)blk * E * (FF / 4)
                           + (size_t)row * (FF / 4);
        const float4* r4 = (const float4*)r_s;
        float a0 = 0.f, a1 = 0.f;
#pragma unroll 8
        for (int j = 0; j < 32; j += 2) {
            a0 += dot4(wrow[lane + 32 * j],       r4[lane + 32 * j]);
            a1 += dot4(wrow[lane + 32 * (j + 1)], r4[lane + 32 * (j + 1)]);
        }
        float acc = a0 + a1;
#pragma unroll
        for (int o = 16; o; o >>= 1) acc += __shfl_xor_sync(0xffffffffu, acc, o);
        if (lane == 0) g_f[cur][row] = acc;
    }
}

// ================= K_CLS: LN2-final + classifier ===========================
// grid = 125 CTAs x 1024. CTA b owns Wc rows [8b, 8b+8).
__global__ void __launch_bounds__(1024)
kcls_kernel(const float* __restrict__ Wc, const float* __restrict__ bc,
            const float* __restrict__ ln2_g, const float* __restrict__ ln2_b)
{
    __shared__ __align__(16) float h_s[E];
    __shared__ float red1[32], red2[32], stats[2];
    __shared__ float red_cls[8][4];

    const int tid = threadIdx.x, lane = tid & 31, wc = tid >> 5;
    const int b = blockIdx.x;
    const int r = wc >> 2, p = wc & 3;         // 8 rows x 4 warp-parts

    // issue Wc loads into registers first (overlap with LN)
    float4 w0, w1;
    {
        const float4* src = (const float4*)Wc + ((size_t)b * 8 + r) * 256;
        w0 = src[p * 64 + lane];
        w1 = src[p * 64 + lane + 32];
    }

    // h_final = LN2 of block 5 (parity: 5&1 = 1)
    {
        float val = g_h1[1][tid] + g_f[1][tid];
        float s1 = val, s2 = val * val;
#pragma unroll
        for (int o = 16; o; o >>= 1) {
            s1 += __shfl_xor_sync(0xffffffffu, s1, o);
            s2 += __shfl_xor_sync(0xffffffffu, s2, o);
        }
        if (lane == 0) { red1[wc] = s1; red2[wc] = s2; }
        __syncthreads();
        if (wc == 0) {
            float a = red1[lane], c = red2[lane];
#pragma unroll
            for (int o = 16; o; o >>= 1) {
                a += __shfl_xor_sync(0xffffffffu, a, o);
                c += __shfl_xor_sync(0xffffffffu, c, o);
            }
            if (lane == 0) {
                float mean = a * (1.0f / E);
                float var  = c * (1.0f / E) - mean * mean;
                stats[0] = mean;
                stats[1] = rsqrtf(fmaxf(var, 0.f) + 1e-5f);
            }
        }
        __syncthreads();
        h_s[tid] = (val - stats[0]) * stats[1] * ln2_g[5 * E + tid]
                 + ln2_b[5 * E + tid];
    }
    __syncthreads();

    const float4* h4 = (const float4*)h_s;
    float acc = dot4(w0, h4[p * 64 + lane]) + dot4(w1, h4[p * 64 + lane + 32]);
#pragma unroll
    for (int o = 16; o; o >>= 1) acc += __shfl_xor_sync(0xffffffffu, acc, o);
    if (lane == 0) red_cls[r][p] = acc;
    __syncthreads();
    if (tid < 8) {
        float s = red_cls[tid][0] + red_cls[tid][1] + red_cls[tid][2] + red_cls[tid][3];
        g_row[b * 8 + tid] = s + bc[b * 8 + tid];
    }
}

// ================= K_BCAST: broadcast row to all B output rows =============
// __stwt: write-through, no L2 allocation.
__global__ void __launch_bounds__(1024)
kb_kernel(float* __restrict__ out)
{
    __shared__ __align__(16) float row_s[CC];
    const int tid = threadIdx.x, lane = tid & 31;
    if (tid < CC) row_s[tid] = g_row[tid];
    __syncthreads();

    const int gwarp = blockIdx.x * 32 + (tid >> 5);
    const int nwarps = gridDim.x * 32;
    const float4* r4 = (const float4*)row_s;               // 250 float4
    for (int r = gwarp; r < BB; r += nwarps) {
        float4* dst = (float4*)out + (size_t)r * (CC / 4);
        for (int j = lane; j < CC / 4; j += 32)
            __stwt(dst + j, r4[j]);
    }
}

// ================= host launch =============================================
extern "C" void kernel_launch(void* const* d_in, const int* in_sizes, int n_in,
                              void* d_out, int out_size) {
    // metadata order: 0:x 1:Wq 2:Wk 3:Wv 4:Wo 5:phi_q 6:W1 7:W2 8:phi_f
    //                 9:ln1_g 10:ln1_b 11:ln2_g 12:ln2_b 13:Wc 14:bc
    const float* Wv    = (const float*)d_in[3];
    const float* Wo    = (const float*)d_in[4];
    const float* phi_q = (const float*)d_in[5];
    const float* W1    = (const float*)d_in[6];
    const float* W2    = (const float*)d_in[7];
    const float* phi_f = (const float*)d_in[8];
    const float* ln1_g = (const float*)d_in[9];
    const float* ln1_b = (const float*)d_in[10];
    const float* ln2_g = (const float*)d_in[11];
    const float* ln2_b = (const float*)d_in[12];
    const float* Wc    = (const float*)d_in[13];
    const float* bc    = (const float*)d_in[14];

    km_kernel<<<192, 256>>>(Wo, Wv);
    for (int blk = 0; blk < NBLK; blk++)
        kf_kernel<<<147, 256>>>(blk, W1, W2, phi_q, phi_f,
                                ln1_g, ln1_b, ln2_g, ln2_b);
    kcls_kernel<<<125, 1024>>>(Wc, bc, ln2_g, ln2_b);
    kb_kernel<<<148, 1024>>>((float*)d_out);
}

// round 15
// speedup vs baseline: 3.7405x; 1.3696x over previous
#include <cuda_runtime.h>
#include <cstdint>

// Problem constants (fixed by the reference)
#define E    1024
#define NBLK 6
#define FF   4096
#define CC   1000
#define BB   4096

// ---------------- device scratch (no allocations allowed) ----------------
__device__ __align__(16) float g_M[NBLK * E * 8]; // precomputed Wo@Wv (E x 8 per block)
__device__ __align__(16) float g_f[2][E];         // f vector, double-buffered by parity
__device__ __align__(16) float g_h1[2][E];        // h-after-LN1, double-buffered
__device__ __align__(16) float g_row[CC];         // classifier row

__device__ __forceinline__ float dot4(float4 a, float4 b) {
    return fmaf(a.x, b.x, fmaf(a.y, b.y, fmaf(a.z, b.z, a.w * b.w)));
}

// ================= K_M: M_blk = Wo_blk @ Wv_blk  (E x 8 per block) =========
// grid = 192 CTAs x 256 threads: CTA c -> blk = c/32, rows (c%32)*32 .. +32.
__global__ void __launch_bounds__(256)
km_kernel(const float* __restrict__ Wo, const float* __restrict__ Wv)
{
    __shared__ __align__(16) float wv_s[E * 8];   // 32KB
    const int tid = threadIdx.x, lane = tid & 31, w = tid >> 5;
    const int blk  = blockIdx.x >> 5;
    const int row0 = (blockIdx.x & 31) * 32;

    const float4* wvg = (const float4*)(Wv + (size_t)blk * E * 8);
    float4* wv4 = (float4*)wv_s;
    for (int i = tid; i < E * 8 / 4; i += 256) wv4[i] = wvg[i];
    __syncthreads();

    const int r0 = row0 + 4 * w;
    const float* wo0 = Wo + (size_t)blk * E * E + (size_t)r0 * E;

    float acc[4][8];
#pragma unroll
    for (int r = 0; r < 4; r++)
#pragma unroll
        for (int j = 0; j < 8; j++) acc[r][j] = 0.f;

#pragma unroll
    for (int kk = 0; kk < 8; kk++) {
        int k4 = lane + 32 * kk;
        float4 wo4[4];
#pragma unroll
        for (int r = 0; r < 4; r++)
            wo4[r] = __ldcs((const float4*)(wo0 + (size_t)r * E) + k4);
#pragma unroll
        for (int q = 0; q < 4; q++) {
            int k = 4 * k4 + q;
            float4 a = wv4[2 * k], c = wv4[2 * k + 1];
#pragma unroll
            for (int r = 0; r < 4; r++) {
                float s = (q == 0) ? wo4[r].x : (q == 1) ? wo4[r].y
                        : (q == 2) ? wo4[r].z : wo4[r].w;
                acc[r][0] = fmaf(s, a.x, acc[r][0]);
                acc[r][1] = fmaf(s, a.y, acc[r][1]);
                acc[r][2] = fmaf(s, a.z, acc[r][2]);
                acc[r][3] = fmaf(s, a.w, acc[r][3]);
                acc[r][4] = fmaf(s, c.x, acc[r][4]);
                acc[r][5] = fmaf(s, c.y, acc[r][5]);
                acc[r][6] = fmaf(s, c.z, acc[r][6]);
                acc[r][7] = fmaf(s, c.w, acc[r][7]);
            }
        }
    }
#pragma unroll
    for (int r = 0; r < 4; r++) {
#pragma unroll
        for (int j = 0; j < 8; j++) {
#pragma unroll
            for (int o = 16; o; o >>= 1)
                acc[r][j] += __shfl_xor_sync(0xffffffffu, acc[r][j], o);
        }
        if (lane == 0) {
            float4* mrow = (float4*)(g_M + ((size_t)blk * E + r0 + r) * 8);
            mrow[0] = make_float4(acc[r][0], acc[r][1], acc[r][2], acc[r][3]);
            mrow[1] = make_float4(acc[r][4], acc[r][5], acc[r][6], acc[r][7]);
        }
    }
}

// ================= K_F(blk): one transformer block ==========================
// grid = 256 CTAs x 512 threads. CTA b owns W2 rows [4b, 4b+4): 16 warps =
// 16 (row, segment) tasks, zero idle warps. ~1.7 CTAs/SM lets the scheduler
// interleave one CTA's serial prologue with the other's W2 load burst.
// W2 slice loaded early into registers (__ldcs: streaming, no reuse);
// prologue overlaps the in-flight loads; then FMA against r_s.
__global__ void __launch_bounds__(512)
kf_kernel(int blk,
          const float* __restrict__ W1,   const float* __restrict__ W2,
          const float* __restrict__ phi_q, const float* __restrict__ phi_f,
          const float* __restrict__ ln1_g, const float* __restrict__ ln1_b,
          const float* __restrict__ ln2_g, const float* __restrict__ ln2_b)
{
    __shared__ __align__(16) float r_s[FF];
    __shared__ __align__(16) float h_s[E];
    __shared__ float red1[16], red2[16], stats[2], m_s[8];
    __shared__ float red_dot[4][4];

    const int tid = threadIdx.x, lane = tid & 31, wc = tid >> 5;  // wc 0..15
    const int b = blockIdx.x;
    const int cur = blk & 1, prev = cur ^ 1;

    const int i = wc >> 2;                 // 0..3 row within CTA
    const int p = wc & 3;                  // 0..3 row segment
    const int row = b * 4 + i;             // 256*4 = 1024 rows exactly

    // ---- 1) issue W2 row-slice loads into registers (fire-and-forget) ----
    float4 wreg[8];
    {
        const float4* src = (const float4*)W2 + (size_t)blk * E * (FF / 4)
                          + (size_t)row * (FF / 4) + p * 256 + lane;
#pragma unroll
        for (int j = 0; j < 8; j++) wreg[j] = __ldcs(src + 32 * j);
    }

    // ---- 2) prologue (overlaps the in-flight loads); 2 h-values/thread ----
    float hp0, hp1;
    {
        int e0 = 2 * tid, e1 = 2 * tid + 1;
        if (blk == 0) {
            hp0 = 1.0f; hp1 = 2.0f;                       // h0 = [1,2,1,2,...]
        } else {
            float v0 = g_h1[prev][e0] + g_f[prev][e0];
            float v1 = g_h1[prev][e1] + g_f[prev][e1];
            float s1 = v0 + v1, s2 = v0 * v0 + v1 * v1;
#pragma unroll
            for (int o = 16; o; o >>= 1) {
                s1 += __shfl_xor_sync(0xffffffffu, s1, o);
                s2 += __shfl_xor_sync(0xffffffffu, s2, o);
            }
            if (lane == 0) { red1[wc] = s1; red2[wc] = s2; }
            __syncthreads();
            if (tid == 0) {
                float t1 = 0.f, t2 = 0.f;
#pragma unroll
                for (int k = 0; k < 16; k++) { t1 += red1[k]; t2 += red2[k]; }
                float mean = t1 * (1.0f / E);
                float var  = t2 * (1.0f / E) - mean * mean;
                stats[0] = mean;
                stats[1] = rsqrtf(fmaxf(var, 0.f) + 1e-5f);
            }
            __syncthreads();
            float mean = stats[0], rstd = stats[1];
            hp0 = (v0 - mean) * rstd * ln2_g[(blk - 1) * E + e0] + ln2_b[(blk - 1) * E + e0];
            hp1 = (v1 - mean) * rstd * ln2_g[(blk - 1) * E + e1] + ln2_b[(blk - 1) * E + e1];
        }
        h_s[e0] = hp0; h_s[e1] = hp1;
    }
    __syncthreads();
    if (tid < 8) m_s[tid] = cosf(h_s[tid] + phi_q[blk * 8 + tid]);
    __syncthreads();

    float h10, h11;
    {
        int e0 = 2 * tid, e1 = 2 * tid + 1;
        const float4* mr0 = (const float4*)(g_M + ((size_t)blk * E + e0) * 8);
        const float4* mr1 = (const float4*)(g_M + ((size_t)blk * E + e1) * 8);
        float4 a0 = mr0[0], c0 = mr0[1];
        float4 a1 = mr1[0], c1 = mr1[1];
        float at0 = a0.x*m_s[0] + a0.y*m_s[1] + a0.z*m_s[2] + a0.w*m_s[3]
                  + c0.x*m_s[4] + c0.y*m_s[5] + c0.z*m_s[6] + c0.w*m_s[7];
        float at1 = a1.x*m_s[0] + a1.y*m_s[1] + a1.z*m_s[2] + a1.w*m_s[3]
                  + c1.x*m_s[4] + c1.y*m_s[5] + c1.z*m_s[6] + c1.w*m_s[7];
        float v0 = hp0 + at0, v1 = hp1 + at1;
        float s1 = v0 + v1, s2 = v0 * v0 + v1 * v1;
#pragma unroll
        for (int o = 16; o; o >>= 1) {
            s1 += __shfl_xor_sync(0xffffffffu, s1, o);
            s2 += __shfl_xor_sync(0xffffffffu, s2, o);
        }
        if (lane == 0) { red1[wc] = s1; red2[wc] = s2; }
        __syncthreads();
        if (tid == 0) {
            float t1 = 0.f, t2 = 0.f;
#pragma unroll
            for (int k = 0; k < 16; k++) { t1 += red1[k]; t2 += red2[k]; }
            float mean = t1 * (1.0f / E);
            float var  = t2 * (1.0f / E) - mean * mean;
            stats[0] = mean;
            stats[1] = rsqrtf(fmaxf(var, 0.f) + 1e-5f);
        }
        __syncthreads();
        float mean = stats[0], rstd = stats[1];
        h10 = (v0 - mean) * rstd * ln1_g[blk * E + e0] + ln1_b[blk * E + e0];
        h11 = (v1 - mean) * rstd * ln1_g[blk * E + e1] + ln1_b[blk * E + e1];
        if (b == 0) { g_h1[cur][e0] = h10; g_h1[cur][e1] = h11; }
        h_s[e0] = h10; h_s[e1] = h11;
    }
    __syncthreads();
    if (tid < 4) m_s[tid] = cosf(h_s[tid]) * cosf(phi_f[blk * 4 + tid]);
    __syncthreads();
    {
        const float4* w1 = (const float4*)W1 + (size_t)blk * FF;  // FF float4 rows
        float m0 = m_s[0], m1 = m_s[1], m2 = m_s[2], m3 = m_s[3];
#pragma unroll
        for (int j = 0; j < FF / 512; j++) {
            int ff = tid + j * 512;
            float4 w = w1[ff];
            r_s[ff] = fmaxf(w.x * m0 + w.y * m1 + w.z * m2 + w.w * m3, 0.f);
        }
    }
    __syncthreads();

    // ---- 3) dot register-resident W2 slice against r ----
    {
        const float4* r4 = (const float4*)r_s;
        float acc = 0.f;
#pragma unroll
        for (int j = 0; j < 8; j++)
            acc += dot4(wreg[j], r4[p * 256 + lane + 32 * j]);
#pragma unroll
        for (int o = 16; o; o >>= 1) acc += __shfl_xor_sync(0xffffffffu, acc, o);
        if (lane == 0) red_dot[i][p] = acc;
    }
    __syncthreads();
    if (tid < 4) {
        float s = red_dot[tid][0] + red_dot[tid][1] + red_dot[tid][2] + red_dot[tid][3];
        g_f[cur][b * 4 + tid] = s;
    }
}

// ================= K_CLS: LN2-final + classifier ===========================
// grid = 125 CTAs x 1024. CTA b owns Wc rows [8b, 8b+8).
__global__ void __launch_bounds__(1024)
kcls_kernel(const float* __restrict__ Wc, const float* __restrict__ bc,
            const float* __restrict__ ln2_g, const float* __restrict__ ln2_b)
{
    __shared__ __align__(16) float h_s[E];
    __shared__ float red1[32], red2[32], stats[2];
    __shared__ float red_cls[8][4];

    const int tid = threadIdx.x, lane = tid & 31, wc = tid >> 5;
    const int b = blockIdx.x;
    const int r = wc >> 2, p = wc & 3;         // 8 rows x 4 warp-parts

    // issue Wc loads into registers first (overlap with LN)
    float4 w0, w1;
    {
        const float4* src = (const float4*)Wc + ((size_t)b * 8 + r) * 256;
        w0 = src[p * 64 + lane];
        w1 = src[p * 64 + lane + 32];
    }

    // h_final = LN2 of block 5 (parity: 5&1 = 1)
    {
        float val = g_h1[1][tid] + g_f[1][tid];
        float s1 = val, s2 = val * val;
#pragma unroll
        for (int o = 16; o; o >>= 1) {
            s1 += __shfl_xor_sync(0xffffffffu, s1, o);
            s2 += __shfl_xor_sync(0xffffffffu, s2, o);
        }
        if (lane == 0) { red1[wc] = s1; red2[wc] = s2; }
        __syncthreads();
        if (wc == 0) {
            float a = red1[lane], c = red2[lane];
#pragma unroll
            for (int o = 16; o; o >>= 1) {
                a += __shfl_xor_sync(0xffffffffu, a, o);
                c += __shfl_xor_sync(0xffffffffu, c, o);
            }
            if (lane == 0) {
                float mean = a * (1.0f / E);
                float var  = c * (1.0f / E) - mean * mean;
                stats[0] = mean;
                stats[1] = rsqrtf(fmaxf(var, 0.f) + 1e-5f);
            }
        }
        __syncthreads();
        h_s[tid] = (val - stats[0]) * stats[1] * ln2_g[5 * E + tid]
                 + ln2_b[5 * E + tid];
    }
    __syncthreads();

    const float4* h4 = (const float4*)h_s;
    float acc = dot4(w0, h4[p * 64 + lane]) + dot4(w1, h4[p * 64 + lane + 32]);
#pragma unroll
    for (int o = 16; o; o >>= 1) acc += __shfl_xor_sync(0xffffffffu, acc, o);
    if (lane == 0) red_cls[r][p] = acc;
    __syncthreads();
    if (tid < 8) {
        float s = red_cls[tid][0] + red_cls[tid][1] + red_cls[tid][2] + red_cls[tid][3];
        g_row[b * 8 + tid] = s + bc[b * 8 + tid];
    }
}

// ================= K_BCAST: broadcast row to all B output rows =============
// __stwt: write-through, no L2 allocation.
__global__ void __launch_bounds__(1024)
kb_kernel(float* __restrict__ out)
{
    __shared__ __align__(16) float row_s[CC];
    const int tid = threadIdx.x, lane = tid & 31;
    if (tid < CC) row_s[tid] = g_row[tid];
    __syncthreads();

    const int gwarp = blockIdx.x * 32 + (tid >> 5);
    const int nwarps = gridDim.x * 32;
    const float4* r4 = (const float4*)row_s;               // 250 float4
    for (int r = gwarp; r < BB; r += nwarps) {
        float4* dst = (float4*)out + (size_t)r * (CC / 4);
        for (int j = lane; j < CC / 4; j += 32)
            __stwt(dst + j, r4[j]);
    }
}

// ================= host launch =============================================
extern "C" void kernel_launch(void* const* d_in, const int* in_sizes, int n_in,
                              void* d_out, int out_size) {
    // metadata order: 0:x 1:Wq 2:Wk 3:Wv 4:Wo 5:phi_q 6:W1 7:W2 8:phi_f
    //                 9:ln1_g 10:ln1_b 11:ln2_g 12:ln2_b 13:Wc 14:bc
    const float* Wv    = (const float*)d_in[3];
    const float* Wo    = (const float*)d_in[4];
    const float* phi_q = (const float*)d_in[5];
    const float* W1    = (const float*)d_in[6];
    const float* W2    = (const float*)d_in[7];
    const float* phi_f = (const float*)d_in[8];
    const float* ln1_g = (const float*)d_in[9];
    const float* ln1_b = (const float*)d_in[10];
    const float* ln2_g = (const float*)d_in[11];
    const float* ln2_b = (const float*)d_in[12];
    const float* Wc    = (const float*)d_in[13];
    const float* bc    = (const float*)d_in[14];

    km_kernel<<<192, 256>>>(Wo, Wv);
    for (int blk = 0; blk < NBLK; blk++)
        kf_kernel<<<256, 512>>>(blk, W1, W2, phi_q, phi_f,
                                ln1_g, ln1_b, ln2_g, ln2_b);
    kcls_kernel<<<125, 1024>>>(Wc, bc, ln2_g, ln2_b);
    kb_kernel<<<148, 1024>>>((float*)d_out);
}